// round 15
// baseline (speedup 1.0000x reference)
#include <cuda_runtime.h>
#include <cuda_fp16.h>
#include <math.h>
#include <stdint.h>

#define LSEQ   2048
#define BATCH  4
#define NT     8192          // BATCH * LSEQ
#define CDIM   256
#define DIN    512
#define DSTATE 16
#define DTRANK 16
#define NCHUNK 32
#define CHLEN  64            // LSEQ / NCHUNK

// ---------------- scratch (static __device__, no allocs) ----------------
__device__ __half g_u    [NT * CDIM];       // (B*L, C) normalized input (fp16)
__device__ __half g_wi   [2 * DIN * CDIM];  // in_proj_w fp16 (1024,256)
__device__ __half g_wo   [CDIM * DIN];      // out_proj_w fp16 (256,512)
__device__ __half g_xz   [2 * DIN * NT];    // (2*DIN, B*L) in_proj out (fp16)
__device__ __half g_xc   [DIN * NT];        // (DIN, B*L) conv+silu (fp16)
__device__ float  g_xpart[4 * 48 * NT];     // x_proj split-K partials
__device__ float  g_Bm   [NT * DSTATE];     // (B*L, 16)
__device__ float  g_Cm   [NT * DSTATE];     // (B*L, 16)
__device__ __half g_delta[DIN * NT];        // (DIN, B*L) softplus (fp16)
__device__ __half g_y    [NT * DIN];        // (B*L, DIN) gated y (fp16)
__device__ float  g_op   [CDIM * NT];       // (C, B*L) out_proj out
__device__ float  g_P    [BATCH * NCHUNK * DIN * DSTATE];
__device__ float  g_q    [BATCH * NCHUNK * DIN * DSTATE];
__device__ float  g_h0   [BATCH * NCHUNK * DIN * DSTATE];

__device__ __forceinline__ uint32_t s2u(const void* p) {
    return (uint32_t)__cvta_generic_to_shared(p);
}
__device__ __forceinline__ void ldsm4(uint32_t* r, uint32_t addr) {
    asm volatile("ldmatrix.sync.aligned.m8n8.x4.shared.b16 {%0,%1,%2,%3}, [%4];"
        : "=r"(r[0]), "=r"(r[1]), "=r"(r[2]), "=r"(r[3]) : "r"(addr));
}
__device__ __forceinline__ void mma16816h(float* c, const uint32_t* a, uint32_t b0, uint32_t b1) {
    asm volatile("mma.sync.aligned.m16n8k16.row.col.f32.f16.f16.f32 "
        "{%0,%1,%2,%3}, {%4,%5,%6,%7}, {%8,%9}, {%0,%1,%2,%3};"
        : "+f"(c[0]), "+f"(c[1]), "+f"(c[2]), "+f"(c[3])
        : "r"(a[0]), "r"(a[1]), "r"(a[2]), "r"(a[3]), "r"(b0), "r"(b1));
}

// ---------------- K0: round both weight matrices to fp16 --------------------
__global__ void cvtw_kernel(const float* __restrict__ wi,
                            const float* __restrict__ wo) {
    int i = blockIdx.x * 256 + threadIdx.x;
    const int n1 = 2 * DIN * CDIM;
    if (i < n1) g_wi[i] = __float2half(wi[i]);
    else        g_wo[i - n1] = __float2half(wo[i - n1]);
}

// ---------------- K1: input LayerNorm (over C), emit fp16 (NT, C) -----------
__global__ void ln_in_kernel(const float* __restrict__ x,
                             const float* __restrict__ w,
                             const float* __restrict__ bias) {
    int b  = blockIdx.y;
    int tid = threadIdx.x;
    int lx = tid & 31;
    int ty = tid >> 5;
    int l0 = blockIdx.x * 32;
    __shared__ float T[CDIM][33];
    __shared__ float sS[8][32], sQ[8][32], sMean[32], sR[32];

    const float* xb = x + (size_t)b * CDIM * LSEQ + l0 + lx;
    float s = 0.f, q = 0.f;
    for (int c = ty; c < CDIM; c += 8) {
        float v = xb[(size_t)c * LSEQ];
        T[c][lx] = v;
        s += v; q += v * v;
    }
    sS[ty][lx] = s; sQ[ty][lx] = q;
    __syncthreads();
    if (ty == 0) {
        float ts = 0.f, tq = 0.f;
        #pragma unroll
        for (int i = 0; i < 8; i++) { ts += sS[i][lx]; tq += sQ[i][lx]; }
        float m   = ts * (1.f / CDIM);
        float var = tq * (1.f / CDIM) - m * m;
        sMean[lx] = m;
        sR[lx]    = rsqrtf(var + 1e-5f);
    }
    __syncthreads();
    int c = tid;
    float wc = w[c], bc = bias[c];
    #pragma unroll 4
    for (int l = 0; l < 32; l++) {
        float v = T[c][l];
        g_u[(size_t)(b * LSEQ + l0 + l) * CDIM + c] =
            __float2half((v - sMean[l]) * sR[l] * wc + bc);
    }
}

// ---------------- K2: TN GEMM, all-fp16 operands ----------------------------
// C[M,N] = A[M,K] * B[N,K]^T.  BM=128 BN=64 BK=32; 8 warps 4(m)x2(n).
template <typename OutT>
__global__ __launch_bounds__(256, 2)
void gemm_h_kernel(const __half* __restrict__ Ag, const __half* __restrict__ Bg,
                   OutT* __restrict__ C, int M, int N, int K) {
    __shared__ __half Ah[128][40], Bh[64][40];
    const int tid = threadIdx.x, lane = tid & 31, wid = tid >> 5;
    const int m0 = blockIdx.y * 128, n0 = blockIdx.x * 64;
    const int wm = (wid & 3) * 32;
    const int wn = (wid >> 2) * 32;
    const int lr = lane & 15;
    const int lc = (lane & 16) ? 8 : 0;

    float acc[2][4][4];
    #pragma unroll
    for (int mi = 0; mi < 2; mi++)
        #pragma unroll
        for (int nf = 0; nf < 4; nf++)
            #pragma unroll
            for (int e = 0; e < 4; e++) acc[mi][nf][e] = 0.f;

    const int ar = tid >> 1;             // A row 0..127
    const int ac = (tid & 1) << 4;       // A half-col 0 or 16
    const int br = tid >> 2;             // B row 0..63
    const int bc8 = (tid & 3) << 3;      // B half-col 0,8,16,24

    const __half* Abase = Ag + (size_t)(m0 + ar) * K + ac;
    const __half* Bbase = Bg + (size_t)(n0 + br) * K + bc8;

    uint4 va0, va1, vb;
    va0 = *(const uint4*)(Abase);
    va1 = *(const uint4*)(Abase + 8);
    vb  = *(const uint4*)(Bbase);

    const int nk = K >> 5;
    for (int kt = 0; kt < nk; kt++) {
        *(uint4*)&Ah[ar][ac]     = va0;
        *(uint4*)&Ah[ar][ac + 8] = va1;
        *(uint4*)&Bh[br][bc8]    = vb;
        __syncthreads();

        if (kt + 1 < nk) {
            const __half* Ap = Abase + (kt + 1) * 32;
            const __half* Bp = Bbase + (kt + 1) * 32;
            va0 = *(const uint4*)(Ap);
            va1 = *(const uint4*)(Ap + 8);
            vb  = *(const uint4*)(Bp);
        }

        #pragma unroll
        for (int kk = 0; kk < 2; kk++) {
            const int k16 = kk * 16;
            uint32_t ah[2][4], bh[2][4];
            #pragma unroll
            for (int mi = 0; mi < 2; mi++)
                ldsm4(ah[mi], s2u(&Ah[wm + mi * 16 + lr][k16 + lc]));
            #pragma unroll
            for (int nj = 0; nj < 2; nj++)
                ldsm4(bh[nj], s2u(&Bh[wn + nj * 16 + lr][k16 + lc]));
            #pragma unroll
            for (int mi = 0; mi < 2; mi++)
                #pragma unroll
                for (int nf = 0; nf < 4; nf++) {
                    int nj = nf >> 1, sub = nf & 1;
                    mma16816h(acc[mi][nf], ah[mi], bh[nj][sub], bh[nj][sub + 2]);
                }
        }
        __syncthreads();
    }

    #pragma unroll
    for (int mi = 0; mi < 2; mi++)
        #pragma unroll
        for (int nf = 0; nf < 4; nf++) {
            int row = m0 + wm + mi * 16 + (lane >> 2);
            int col = n0 + wn + nf * 8 + ((lane & 3) << 1);
            if constexpr (sizeof(OutT) == 2) {
                __half2 h0, h1;
                h0.x = __float2half(acc[mi][nf][0]); h0.y = __float2half(acc[mi][nf][1]);
                h1.x = __float2half(acc[mi][nf][2]); h1.y = __float2half(acc[mi][nf][3]);
                *(__half2*)&C[(size_t)row * N + col]       = h0;
                *(__half2*)&C[(size_t)(row + 8) * N + col] = h1;
            } else {
                float2 v0; v0.x = acc[mi][nf][0]; v0.y = acc[mi][nf][1];
                float2 v1; v1.x = acc[mi][nf][2]; v1.y = acc[mi][nf][3];
                *(float2*)&C[(size_t)row * N + col]       = v0;
                *(float2*)&C[(size_t)(row + 8) * N + col] = v1;
            }
        }
}

// ---------------- K3: x_proj split-K partials + fused conv+SiLU -------------
__global__ void xproj_part_kernel(const float* __restrict__ W,
                                  const float* __restrict__ cw,
                                  const float* __restrict__ cb) {
    __shared__ float Ws[48][64];
    __shared__ float Xr[64][68];     // raw xz, col j <-> n0-4+j
    __shared__ float Xs[64][68];     // conv+silu, col c <-> n0+c
    __shared__ float Cw[64][4];
    __shared__ float Cb[64];
    int t  = threadIdx.x;
    int n0 = blockIdx.x * 64;
    int ks = blockIdx.y;
    int tn = t & 63, tk = t >> 6;
    bool seqstart = (n0 & (LSEQ - 1)) == 0;
    float acc[12];
    #pragma unroll
    for (int j = 0; j < 12; j++) acc[j] = 0.f;

    for (int cc = 0; cc < 2; cc++) {
        int d0 = ks * 128 + cc * 64;
        __syncthreads();
        for (int i = t; i < 768; i += 256) {
            int r = i >> 4, c4 = (i & 15) << 2;
            *(float4*)&Ws[r][c4] = *(const float4*)&W[(size_t)r * DIN + d0 + c4];
        }
        if (t < 64) {
            *(float4*)&Cw[t][0] = *(const float4*)&cw[(d0 + t) * 4];
            Cb[t] = cb[d0 + t];
        }
        for (int i = t; i < 512; i += 256) {
            int r = i >> 3, c8 = (i & 7) << 3;
            uint4 raw = *(const uint4*)&g_xz[(size_t)(d0 + r) * NT + n0 + c8];
            const __half2* hp = (const __half2*)&raw;
            #pragma unroll
            for (int j = 0; j < 4; j++) {
                float2 f = __half22float2(hp[j]);
                Xr[r][4 + c8 + j * 2]     = f.x;
                Xr[r][4 + c8 + j * 2 + 1] = f.y;
            }
        }
        if (t < 192) {                              // history cols j=1..3
            int r = t / 3, j = t - r * 3;
            Xr[r][1 + j] = seqstart ? 0.f
                : __half2float(g_xz[(size_t)(d0 + r) * NT + n0 - 3 + j]);
        }
        __syncthreads();
        for (int i = t; i < 4096; i += 256) {
            int r = i >> 6, c = i & 63;
            float v = Cb[r];
            v = fmaf(Cw[r][3], Xr[r][c + 4], v);
            v = fmaf(Cw[r][2], Xr[r][c + 3], v);
            v = fmaf(Cw[r][1], Xr[r][c + 2], v);
            v = fmaf(Cw[r][0], Xr[r][c + 1], v);
            float xc = v / (1.f + __expf(-v));
            Xs[r][c] = xc;
            g_xc[(size_t)(d0 + r) * NT + n0 + c] = __float2half(xc);
        }
        __syncthreads();
        #pragma unroll 4
        for (int dd = 0; dd < 64; dd++) {
            float xv = Xs[dd][tn];
            #pragma unroll
            for (int j = 0; j < 12; j++)
                acc[j] = fmaf(xv, Ws[tk * 12 + j][dd], acc[j]);
        }
    }
    int n = n0 + tn;
    #pragma unroll
    for (int j = 0; j < 12; j++) {
        int k = tk * 12 + j;
        g_xpart[((size_t)ks * 48 + k) * NT + n] = acc[j];
    }
}

// ---------------- K4: fused xred + delta ------------------------------------
// grid (NT/256, 4). Block reduces dt-partials for its 256 n's into smem,
// computes delta for its 128-d segment. dseg==0 blocks also write Bm/Cm.
__global__ void delta_kernel(const float* __restrict__ dtw,
                             const float* __restrict__ dtb) {
    __shared__ float sDt[256][17];
    __shared__ float sW[128][17];
    __shared__ float sB[128];
    int t = threadIdx.x;
    int n0 = blockIdx.x * 256;
    int dseg = blockIdx.y * 128;
    int n = n0 + t;

    // reduce dt partials (k = 0..15) for this n
    #pragma unroll
    for (int k = 0; k < DTRANK; k++) {
        float s = g_xpart[(size_t)k * NT + n]
                + g_xpart[((size_t)48 + k) * NT + n]
                + g_xpart[((size_t)96 + k) * NT + n]
                + g_xpart[((size_t)144 + k) * NT + n];
        sDt[t][k] = s;
    }
    // dseg==0 blocks also produce Bm/Cm for this n-range
    if (blockIdx.y == 0) {
        #pragma unroll
        for (int k = DTRANK; k < 48; k++) {
            float s = g_xpart[(size_t)k * NT + n]
                    + g_xpart[((size_t)48 + k) * NT + n]
                    + g_xpart[((size_t)96 + k) * NT + n]
                    + g_xpart[((size_t)144 + k) * NT + n];
            if (k < DTRANK + DSTATE) g_Bm[(size_t)n * 16 + (k - DTRANK)] = s;
            else                     g_Cm[(size_t)n * 16 + (k - DTRANK - DSTATE)] = s;
        }
    }
    for (int i = t; i < 128 * 4; i += 256) {
        int r = i >> 2, c4 = (i & 3) << 2;
        float4 v = *(const float4*)&dtw[(size_t)(dseg + r) * 16 + c4];
        sW[r][c4 + 0] = v.x; sW[r][c4 + 1] = v.y;
        sW[r][c4 + 2] = v.z; sW[r][c4 + 3] = v.w;
    }
    if (t < 128) sB[t] = dtb[dseg + t];
    __syncthreads();

    for (int dd = 0; dd < 128; dd++) {
        float s = sB[dd];
        #pragma unroll
        for (int k = 0; k < 16; k++)
            s = fmaf(sDt[t][k], sW[dd][k], s);
        float delta = (s > 20.f) ? s : log1pf(__expf(s));
        g_delta[(size_t)(dseg + dd) * NT + n] = __float2half(delta);
    }
}

// ---------------- K5a: chunk scan pass1 — smem-shared B chunk ---------------
__global__ void scan_p1_kernel(const float* __restrict__ Alog) {
    __shared__ float sB[CHLEN][16];
    int b  = blockIdx.z;
    int ch = blockIdx.y;
    int g  = threadIdx.x >> 4;
    int nl = threadIdx.x & 15;
    int d0 = blockIdx.x * 128;
    int base = b * LSEQ + ch * CHLEN;

    {
        int t = threadIdx.x;
        float4 v = *(const float4*)&g_Bm[((size_t)base) * 16 + t * 4];
        *(float4*)&sB[(t * 4) >> 4][(t * 4) & 15] = v;
    }
    __syncthreads();

    for (int dt = 0; dt < 8; dt++) {
        int d = d0 + dt * 16 + g;
        float Adn = -__expf(Alog[d * DSTATE + nl]);
        float P = 1.f, q = 0.f;
        const __half* drow  = g_delta + (size_t)d * NT + base;
        const __half* xcrow = g_xc    + (size_t)d * NT + base;
        #pragma unroll 4
        for (int l = 0; l < CHLEN; l++) {
            float delta = __half2float(drow[l]);
            float dA = __expf(delta * Adn);
            q = fmaf(dA, q, delta * sB[l][nl] * __half2float(xcrow[l]));
            P *= dA;
        }
        size_t idx = ((size_t)(b * NCHUNK + ch) * DIN + d) * 16 + nl;
        g_P[idx] = P;
        g_q[idx] = q;
    }
}

// ---------------- K5b: prefix over chunks -> h0 -----------------------------
__global__ void scan_p2_kernel() {
    int idx = blockIdx.x * 256 + threadIdx.x;
    int n = idx & 15;
    int d = (idx >> 4) & (DIN - 1);
    int b = idx >> 13;
    float h = 0.f;
    #pragma unroll
    for (int ch = 0; ch < NCHUNK; ch++) {
        size_t p = ((size_t)(b * NCHUNK + ch) * DIN + d) * 16 + n;
        g_h0[p] = h;
        h = fmaf(g_P[p], h, g_q[p]);
    }
}

// ---------------- K5c: replay + y + gating — emit y fp16 (NT, DIN) ----------
__global__ void scan_p3_kernel(const float* __restrict__ Alog,
                               const float* __restrict__ Dp) {
    __shared__ float sB[CHLEN][16];
    __shared__ float sC[CHLEN][16];
    int b  = blockIdx.z;
    int ch = blockIdx.y;
    int g  = threadIdx.x >> 4;
    int nl = threadIdx.x & 15;
    int d0 = blockIdx.x * 128;
    int base = b * LSEQ + ch * CHLEN;

    {
        int t = threadIdx.x;
        float4 v = *(const float4*)&g_Bm[((size_t)base) * 16 + t * 4];
        *(float4*)&sB[(t * 4) >> 4][(t * 4) & 15] = v;
        float4 w = *(const float4*)&g_Cm[((size_t)base) * 16 + t * 4];
        *(float4*)&sC[(t * 4) >> 4][(t * 4) & 15] = w;
    }
    __syncthreads();

    for (int dt = 0; dt < 8; dt++) {
        int d = d0 + dt * 16 + g;
        float Adn = -__expf(Alog[d * DSTATE + nl]);
        float Dd  = Dp[d];
        float h = g_h0[((size_t)(b * NCHUNK + ch) * DIN + d) * 16 + nl];
        const __half* drow  = g_delta + (size_t)d * NT + base;
        const __half* xcrow = g_xc    + (size_t)d * NT + base;
        const __half* zrow  = g_xz + (size_t)(DIN + d) * NT + base;
        #pragma unroll 4
        for (int l = 0; l < CHLEN; l++) {
            float delta = __half2float(drow[l]);
            float xcv = __half2float(xcrow[l]);
            float dA = __expf(delta * Adn);
            h = fmaf(dA, h, delta * sB[l][nl] * xcv);
            float yv = h * sC[l][nl];
            yv += __shfl_xor_sync(0xffffffffu, yv, 1);
            yv += __shfl_xor_sync(0xffffffffu, yv, 2);
            yv += __shfl_xor_sync(0xffffffffu, yv, 4);
            yv += __shfl_xor_sync(0xffffffffu, yv, 8);
            if (nl == 0) {
                float zl = __half2float(zrow[l]);
                float silu = zl / (1.f + __expf(-zl));
                g_y[(size_t)(base + l) * DIN + d] =
                    __float2half((yv + Dd * xcv) * silu);
            }
        }
    }
}

// ---------------- K6: residual + output LayerNorm, write (B,C,L,1) ----------
__global__ void ln_out_kernel(const float* __restrict__ x,
                              const float* __restrict__ w,
                              const float* __restrict__ bias,
                              float* __restrict__ out) {
    int b  = blockIdx.y;
    int lx = threadIdx.x;
    int ty = threadIdx.y;
    int l  = blockIdx.x * 32 + lx;
    __shared__ float sS[8][32], sQ[8][32], sMean[32], sR[32];

    const float* xb = x + (size_t)b * CDIM * LSEQ + l;
    const float* ob = g_op + (size_t)b * LSEQ + l;
    float s = 0.f, q = 0.f;
    for (int c = ty; c < CDIM; c += 8) {
        float v = ob[(size_t)c * NT] + xb[(size_t)c * LSEQ];
        s += v; q += v * v;
    }
    sS[ty][lx] = s; sQ[ty][lx] = q;
    __syncthreads();
    if (ty == 0) {
        float ts = 0.f, tq = 0.f;
        #pragma unroll
        for (int i = 0; i < 8; i++) { ts += sS[i][lx]; tq += sQ[i][lx]; }
        float m   = ts * (1.f / CDIM);
        float var = tq * (1.f / CDIM) - m * m;
        sMean[lx] = m;
        sR[lx]    = rsqrtf(var + 1e-5f);
    }
    __syncthreads();
    float m = sMean[lx], r = sR[lx];
    float* outb = out + (size_t)b * CDIM * LSEQ + l;
    for (int c = ty; c < CDIM; c += 8) {
        float v = ob[(size_t)c * NT] + xb[(size_t)c * LSEQ];
        outb[(size_t)c * LSEQ] = (v - m) * r * w[c] + bias[c];
    }
}

// ---------------- launch -----------------------------------------------------
extern "C" void kernel_launch(void* const* d_in, const int* in_sizes, int n_in,
                              void* d_out, int out_size) {
    const float* x         = (const float*)d_in[0];
    const float* ln_w      = (const float*)d_in[1];
    const float* ln_b      = (const float*)d_in[2];
    const float* in_proj_w = (const float*)d_in[3];
    const float* conv_w    = (const float*)d_in[4];
    const float* conv_b    = (const float*)d_in[5];
    const float* x_proj_w  = (const float*)d_in[6];
    const float* dt_proj_w = (const float*)d_in[7];
    const float* dt_proj_b = (const float*)d_in[8];
    const float* A_log     = (const float*)d_in[9];
    const float* Dv        = (const float*)d_in[10];
    const float* out_proj_w= (const float*)d_in[11];
    float* out = (float*)d_out;

    __half *p_u, *p_xz, *p_y, *p_wi, *p_wo;
    float  *p_op;
    cudaGetSymbolAddress((void**)&p_u,  g_u);
    cudaGetSymbolAddress((void**)&p_xz, g_xz);
    cudaGetSymbolAddress((void**)&p_y,  g_y);
    cudaGetSymbolAddress((void**)&p_wi, g_wi);
    cudaGetSymbolAddress((void**)&p_wo, g_wo);
    cudaGetSymbolAddress((void**)&p_op, g_op);

    cvtw_kernel<<<(2 * DIN * CDIM + CDIM * DIN) / 256, 256>>>(in_proj_w, out_proj_w);

    ln_in_kernel<<<dim3(LSEQ / 32, BATCH), 256>>>(x, ln_w, ln_b);

    // in_proj: (1024,256) @ (8192,256)^T -> fp16 output
    gemm_h_kernel<__half><<<dim3(NT / 64, (2 * DIN) / 128), 256>>>(
        p_wi, p_u, p_xz, 2 * DIN, NT, CDIM);

    xproj_part_kernel<<<dim3(NT / 64, 4), 256>>>(x_proj_w, conv_w, conv_b);

    delta_kernel<<<dim3(NT / 256, 4), 256>>>(dt_proj_w, dt_proj_b);

    scan_p1_kernel<<<dim3(4, NCHUNK, BATCH), 256>>>(A_log);
    scan_p2_kernel<<<dim3(BATCH * DIN * 16 / 256), 256>>>();
    scan_p3_kernel<<<dim3(4, NCHUNK, BATCH), 256>>>(A_log, Dv);

    // out_proj: (256,512) @ (8192,512)^T -> fp32 output
    gemm_h_kernel<float><<<dim3(NT / 64, CDIM / 128), 256>>>(
        p_wo, p_y, p_op, CDIM, NT, DIN);

    ln_out_kernel<<<dim3(LSEQ / 32, BATCH), dim3(32, 8)>>>(x, ln_w, ln_b, out);
}

// round 16
// speedup vs baseline: 1.0248x; 1.0248x over previous
#include <cuda_runtime.h>
#include <cuda_fp16.h>
#include <math.h>
#include <stdint.h>

#define LSEQ   2048
#define BATCH  4
#define NT     8192          // BATCH * LSEQ
#define CDIM   256
#define DIN    512
#define DSTATE 16
#define DTRANK 16
#define NCHUNK 32
#define CHLEN  64            // LSEQ / NCHUNK

// ---------------- scratch (static __device__, no allocs) ----------------
__device__ __half g_u    [NT * CDIM];       // (B*L, C) normalized input (fp16)
__device__ __half g_wi   [2 * DIN * CDIM];  // in_proj_w fp16 (1024,256)
__device__ __half g_wo   [CDIM * DIN];      // out_proj_w fp16 (256,512)
__device__ __half g_xz   [2 * DIN * NT];    // (2*DIN, B*L) in_proj out (fp16)
__device__ __half g_xc   [DIN * NT];        // (DIN, B*L) conv+silu (fp16)
__device__ float  g_xpart[4 * 48 * NT];     // x_proj split-K partials
__device__ float  g_dt   [NT * DTRANK];     // (B*L, 16)
__device__ float  g_Bm   [NT * DSTATE];     // (B*L, 16)
__device__ float  g_Cm   [NT * DSTATE];     // (B*L, 16)
__device__ __half g_delta[DIN * NT];        // (DIN, B*L) softplus (fp16)
__device__ __half g_y    [NT * DIN];        // (B*L, DIN) gated y (fp16)
__device__ float  g_op   [CDIM * NT];       // (C, B*L) out_proj out
__device__ float  g_P    [BATCH * NCHUNK * DIN * DSTATE];
__device__ float  g_q    [BATCH * NCHUNK * DIN * DSTATE];
__device__ float  g_h0   [BATCH * NCHUNK * DIN * DSTATE];

__device__ __forceinline__ uint32_t s2u(const void* p) {
    return (uint32_t)__cvta_generic_to_shared(p);
}
__device__ __forceinline__ void ldsm4(uint32_t* r, uint32_t addr) {
    asm volatile("ldmatrix.sync.aligned.m8n8.x4.shared.b16 {%0,%1,%2,%3}, [%4];"
        : "=r"(r[0]), "=r"(r[1]), "=r"(r[2]), "=r"(r[3]) : "r"(addr));
}
__device__ __forceinline__ void mma16816h(float* c, const uint32_t* a, uint32_t b0, uint32_t b1) {
    asm volatile("mma.sync.aligned.m16n8k16.row.col.f32.f16.f16.f32 "
        "{%0,%1,%2,%3}, {%4,%5,%6,%7}, {%8,%9}, {%0,%1,%2,%3};"
        : "+f"(c[0]), "+f"(c[1]), "+f"(c[2]), "+f"(c[3])
        : "r"(a[0]), "r"(a[1]), "r"(a[2]), "r"(a[3]), "r"(b0), "r"(b1));
}

// ---------------- K0: round both weight matrices to fp16 --------------------
__global__ void cvtw_kernel(const float* __restrict__ wi,
                            const float* __restrict__ wo) {
    int i = blockIdx.x * 256 + threadIdx.x;
    const int n1 = 2 * DIN * CDIM;
    if (i < n1) g_wi[i] = __float2half(wi[i]);
    else        g_wo[i - n1] = __float2half(wo[i - n1]);
}

// ---------------- K1: input LayerNorm (over C), emit fp16 (NT, C) -----------
__global__ void ln_in_kernel(const float* __restrict__ x,
                             const float* __restrict__ w,
                             const float* __restrict__ bias) {
    int b  = blockIdx.y;
    int tid = threadIdx.x;
    int lx = tid & 31;
    int ty = tid >> 5;
    int l0 = blockIdx.x * 32;
    __shared__ float T[CDIM][33];
    __shared__ float sS[8][32], sQ[8][32], sMean[32], sR[32];

    const float* xb = x + (size_t)b * CDIM * LSEQ + l0 + lx;
    float s = 0.f, q = 0.f;
    for (int c = ty; c < CDIM; c += 8) {
        float v = xb[(size_t)c * LSEQ];
        T[c][lx] = v;
        s += v; q += v * v;
    }
    sS[ty][lx] = s; sQ[ty][lx] = q;
    __syncthreads();
    if (ty == 0) {
        float ts = 0.f, tq = 0.f;
        #pragma unroll
        for (int i = 0; i < 8; i++) { ts += sS[i][lx]; tq += sQ[i][lx]; }
        float m   = ts * (1.f / CDIM);
        float var = tq * (1.f / CDIM) - m * m;
        sMean[lx] = m;
        sR[lx]    = rsqrtf(var + 1e-5f);
    }
    __syncthreads();
    int c = tid;
    float wc = w[c], bc = bias[c];
    #pragma unroll 4
    for (int l = 0; l < 32; l++) {
        float v = T[c][l];
        g_u[(size_t)(b * LSEQ + l0 + l) * CDIM + c] =
            __float2half((v - sMean[l]) * sR[l] * wc + bc);
    }
}

// ---------------- K2: TN GEMM, all-fp16 operands ----------------------------
// C[M,N] = A[M,K] * B[N,K]^T.  BM=128 BN=64 BK=32; 8 warps 4(m)x2(n).
template <typename OutT>
__global__ __launch_bounds__(256, 2)
void gemm_h_kernel(const __half* __restrict__ Ag, const __half* __restrict__ Bg,
                   OutT* __restrict__ C, int M, int N, int K) {
    __shared__ __half Ah[128][40], Bh[64][40];
    const int tid = threadIdx.x, lane = tid & 31, wid = tid >> 5;
    const int m0 = blockIdx.y * 128, n0 = blockIdx.x * 64;
    const int wm = (wid & 3) * 32;
    const int wn = (wid >> 2) * 32;
    const int lr = lane & 15;
    const int lc = (lane & 16) ? 8 : 0;

    float acc[2][4][4];
    #pragma unroll
    for (int mi = 0; mi < 2; mi++)
        #pragma unroll
        for (int nf = 0; nf < 4; nf++)
            #pragma unroll
            for (int e = 0; e < 4; e++) acc[mi][nf][e] = 0.f;

    const int ar = tid >> 1;             // A row 0..127
    const int ac = (tid & 1) << 4;       // A half-col 0 or 16
    const int br = tid >> 2;             // B row 0..63
    const int bc8 = (tid & 3) << 3;      // B half-col 0,8,16,24

    const __half* Abase = Ag + (size_t)(m0 + ar) * K + ac;
    const __half* Bbase = Bg + (size_t)(n0 + br) * K + bc8;

    uint4 va0, va1, vb;
    va0 = *(const uint4*)(Abase);
    va1 = *(const uint4*)(Abase + 8);
    vb  = *(const uint4*)(Bbase);

    const int nk = K >> 5;
    for (int kt = 0; kt < nk; kt++) {
        *(uint4*)&Ah[ar][ac]     = va0;
        *(uint4*)&Ah[ar][ac + 8] = va1;
        *(uint4*)&Bh[br][bc8]    = vb;
        __syncthreads();

        if (kt + 1 < nk) {
            const __half* Ap = Abase + (kt + 1) * 32;
            const __half* Bp = Bbase + (kt + 1) * 32;
            va0 = *(const uint4*)(Ap);
            va1 = *(const uint4*)(Ap + 8);
            vb  = *(const uint4*)(Bp);
        }

        #pragma unroll
        for (int kk = 0; kk < 2; kk++) {
            const int k16 = kk * 16;
            uint32_t ah[2][4], bh[2][4];
            #pragma unroll
            for (int mi = 0; mi < 2; mi++)
                ldsm4(ah[mi], s2u(&Ah[wm + mi * 16 + lr][k16 + lc]));
            #pragma unroll
            for (int nj = 0; nj < 2; nj++)
                ldsm4(bh[nj], s2u(&Bh[wn + nj * 16 + lr][k16 + lc]));
            #pragma unroll
            for (int mi = 0; mi < 2; mi++)
                #pragma unroll
                for (int nf = 0; nf < 4; nf++) {
                    int nj = nf >> 1, sub = nf & 1;
                    mma16816h(acc[mi][nf], ah[mi], bh[nj][sub], bh[nj][sub + 2]);
                }
        }
        __syncthreads();
    }

    #pragma unroll
    for (int mi = 0; mi < 2; mi++)
        #pragma unroll
        for (int nf = 0; nf < 4; nf++) {
            int row = m0 + wm + mi * 16 + (lane >> 2);
            int col = n0 + wn + nf * 8 + ((lane & 3) << 1);
            if constexpr (sizeof(OutT) == 2) {
                __half2 h0, h1;
                h0.x = __float2half(acc[mi][nf][0]); h0.y = __float2half(acc[mi][nf][1]);
                h1.x = __float2half(acc[mi][nf][2]); h1.y = __float2half(acc[mi][nf][3]);
                *(__half2*)&C[(size_t)row * N + col]       = h0;
                *(__half2*)&C[(size_t)(row + 8) * N + col] = h1;
            } else {
                float2 v0; v0.x = acc[mi][nf][0]; v0.y = acc[mi][nf][1];
                float2 v1; v1.x = acc[mi][nf][2]; v1.y = acc[mi][nf][3];
                *(float2*)&C[(size_t)row * N + col]       = v0;
                *(float2*)&C[(size_t)(row + 8) * N + col] = v1;
            }
        }
}

// ---------------- K3: x_proj split-K partials + fused conv+SiLU -------------
__global__ void xproj_part_kernel(const float* __restrict__ W,
                                  const float* __restrict__ cw,
                                  const float* __restrict__ cb) {
    __shared__ float Ws[48][64];
    __shared__ float Xr[64][68];     // raw xz, col j <-> n0-4+j
    __shared__ float Xs[64][68];     // conv+silu, col c <-> n0+c
    __shared__ float Cw[64][4];
    __shared__ float Cb[64];
    int t  = threadIdx.x;
    int n0 = blockIdx.x * 64;
    int ks = blockIdx.y;
    int tn = t & 63, tk = t >> 6;
    bool seqstart = (n0 & (LSEQ - 1)) == 0;
    float acc[12];
    #pragma unroll
    for (int j = 0; j < 12; j++) acc[j] = 0.f;

    for (int cc = 0; cc < 2; cc++) {
        int d0 = ks * 128 + cc * 64;
        __syncthreads();
        for (int i = t; i < 768; i += 256) {
            int r = i >> 4, c4 = (i & 15) << 2;
            *(float4*)&Ws[r][c4] = *(const float4*)&W[(size_t)r * DIN + d0 + c4];
        }
        if (t < 64) {
            *(float4*)&Cw[t][0] = *(const float4*)&cw[(d0 + t) * 4];
            Cb[t] = cb[d0 + t];
        }
        for (int i = t; i < 512; i += 256) {
            int r = i >> 3, c8 = (i & 7) << 3;
            uint4 raw = *(const uint4*)&g_xz[(size_t)(d0 + r) * NT + n0 + c8];
            const __half2* hp = (const __half2*)&raw;
            #pragma unroll
            for (int j = 0; j < 4; j++) {
                float2 f = __half22float2(hp[j]);
                Xr[r][4 + c8 + j * 2]     = f.x;
                Xr[r][4 + c8 + j * 2 + 1] = f.y;
            }
        }
        if (t < 192) {                              // history cols j=1..3
            int r = t / 3, j = t - r * 3;
            Xr[r][1 + j] = seqstart ? 0.f
                : __half2float(g_xz[(size_t)(d0 + r) * NT + n0 - 3 + j]);
        }
        __syncthreads();
        for (int i = t; i < 4096; i += 256) {
            int r = i >> 6, c = i & 63;
            float v = Cb[r];
            v = fmaf(Cw[r][3], Xr[r][c + 4], v);
            v = fmaf(Cw[r][2], Xr[r][c + 3], v);
            v = fmaf(Cw[r][1], Xr[r][c + 2], v);
            v = fmaf(Cw[r][0], Xr[r][c + 1], v);
            float xc = v / (1.f + __expf(-v));
            Xs[r][c] = xc;
            g_xc[(size_t)(d0 + r) * NT + n0 + c] = __float2half(xc);
        }
        __syncthreads();
        #pragma unroll 4
        for (int dd = 0; dd < 64; dd++) {
            float xv = Xs[dd][tn];
            #pragma unroll
            for (int j = 0; j < 12; j++)
                acc[j] = fmaf(xv, Ws[tk * 12 + j][dd], acc[j]);
        }
    }
    int n = n0 + tn;
    #pragma unroll
    for (int j = 0; j < 12; j++) {
        int k = tk * 12 + j;
        g_xpart[((size_t)ks * 48 + k) * NT + n] = acc[j];
    }
}

// ---------------- K4: reduce partials -> dt/Bm/Cm in (n,16) layout ----------
__global__ void xred_kernel() {
    int idx = blockIdx.x * 256 + threadIdx.x;       // 48 * NT
    int k = idx / NT, n = idx - k * NT;
    float s = g_xpart[(size_t)k * NT + n]
            + g_xpart[((size_t)48 + k) * NT + n]
            + g_xpart[((size_t)96 + k) * NT + n]
            + g_xpart[((size_t)144 + k) * NT + n];
    if (k < DTRANK)                g_dt[(size_t)n * 16 + k] = s;
    else if (k < DTRANK + DSTATE)  g_Bm[(size_t)n * 16 + (k - DTRANK)] = s;
    else                           g_Cm[(size_t)n * 16 + (k - DTRANK - DSTATE)] = s;
}

// ---------------- K5: delta = softplus(dt @ dtw^T + dtb), smem-tiled --------
__global__ void delta_kernel(const float* __restrict__ dtw,
                             const float* __restrict__ dtb) {
    __shared__ float sDt[256][17];
    __shared__ float sW[128][17];
    __shared__ float sB[128];
    int t = threadIdx.x;
    int n0 = blockIdx.x * 256;
    int dseg = blockIdx.y * 128;

    for (int i = t; i < 256 * 4; i += 256) {
        int r = i >> 2, c4 = (i & 3) << 2;
        float4 v = *(const float4*)&g_dt[(size_t)(n0 + r) * 16 + c4];
        sDt[r][c4 + 0] = v.x; sDt[r][c4 + 1] = v.y;
        sDt[r][c4 + 2] = v.z; sDt[r][c4 + 3] = v.w;
    }
    for (int i = t; i < 128 * 4; i += 256) {
        int r = i >> 2, c4 = (i & 3) << 2;
        float4 v = *(const float4*)&dtw[(size_t)(dseg + r) * 16 + c4];
        sW[r][c4 + 0] = v.x; sW[r][c4 + 1] = v.y;
        sW[r][c4 + 2] = v.z; sW[r][c4 + 3] = v.w;
    }
    if (t < 128) sB[t] = dtb[dseg + t];
    __syncthreads();

    int n = n0 + t;
    for (int dd = 0; dd < 128; dd++) {
        float s = sB[dd];
        #pragma unroll
        for (int k = 0; k < 16; k++)
            s = fmaf(sDt[t][k], sW[dd][k], s);
        float delta = (s > 20.f) ? s : log1pf(__expf(s));
        g_delta[(size_t)(dseg + dd) * NT + n] = __float2half(delta);
    }
}

// ---------------- K6a: chunk scan pass1 — smem-shared B chunk ---------------
__global__ void scan_p1_kernel(const float* __restrict__ Alog) {
    __shared__ float sB[CHLEN][16];
    int b  = blockIdx.z;
    int ch = blockIdx.y;
    int g  = threadIdx.x >> 4;
    int nl = threadIdx.x & 15;
    int d0 = blockIdx.x * 128;
    int base = b * LSEQ + ch * CHLEN;

    {
        int t = threadIdx.x;
        float4 v = *(const float4*)&g_Bm[((size_t)base) * 16 + t * 4];
        *(float4*)&sB[(t * 4) >> 4][(t * 4) & 15] = v;
    }
    __syncthreads();

    for (int dt = 0; dt < 8; dt++) {
        int d = d0 + dt * 16 + g;
        float Adn = -__expf(Alog[d * DSTATE + nl]);
        float P = 1.f, q = 0.f;
        const __half* drow  = g_delta + (size_t)d * NT + base;
        const __half* xcrow = g_xc    + (size_t)d * NT + base;
        #pragma unroll 4
        for (int l = 0; l < CHLEN; l++) {
            float delta = __half2float(drow[l]);
            float dA = __expf(delta * Adn);
            q = fmaf(dA, q, delta * sB[l][nl] * __half2float(xcrow[l]));
            P *= dA;
        }
        size_t idx = ((size_t)(b * NCHUNK + ch) * DIN + d) * 16 + nl;
        g_P[idx] = P;
        g_q[idx] = q;
    }
}

// ---------------- K6b: prefix over chunks -> h0 -----------------------------
__global__ void scan_p2_kernel() {
    int idx = blockIdx.x * 256 + threadIdx.x;
    int n = idx & 15;
    int d = (idx >> 4) & (DIN - 1);
    int b = idx >> 13;
    float h = 0.f;
    #pragma unroll
    for (int ch = 0; ch < NCHUNK; ch++) {
        size_t p = ((size_t)(b * NCHUNK + ch) * DIN + d) * 16 + n;
        g_h0[p] = h;
        h = fmaf(g_P[p], h, g_q[p]);
    }
}

// ---------------- K6c: replay + y + gating — emit y fp16 (NT, DIN) ----------
__global__ void scan_p3_kernel(const float* __restrict__ Alog,
                               const float* __restrict__ Dp) {
    __shared__ float sB[CHLEN][16];
    __shared__ float sC[CHLEN][16];
    int b  = blockIdx.z;
    int ch = blockIdx.y;
    int g  = threadIdx.x >> 4;
    int nl = threadIdx.x & 15;
    int d0 = blockIdx.x * 128;
    int base = b * LSEQ + ch * CHLEN;

    {
        int t = threadIdx.x;
        float4 v = *(const float4*)&g_Bm[((size_t)base) * 16 + t * 4];
        *(float4*)&sB[(t * 4) >> 4][(t * 4) & 15] = v;
        float4 w = *(const float4*)&g_Cm[((size_t)base) * 16 + t * 4];
        *(float4*)&sC[(t * 4) >> 4][(t * 4) & 15] = w;
    }
    __syncthreads();

    for (int dt = 0; dt < 8; dt++) {
        int d = d0 + dt * 16 + g;
        float Adn = -__expf(Alog[d * DSTATE + nl]);
        float Dd  = Dp[d];
        float h = g_h0[((size_t)(b * NCHUNK + ch) * DIN + d) * 16 + nl];
        const __half* drow  = g_delta + (size_t)d * NT + base;
        const __half* xcrow = g_xc    + (size_t)d * NT + base;
        const __half* zrow  = g_xz + (size_t)(DIN + d) * NT + base;
        #pragma unroll 4
        for (int l = 0; l < CHLEN; l++) {
            float delta = __half2float(drow[l]);
            float xcv = __half2float(xcrow[l]);
            float dA = __expf(delta * Adn);
            h = fmaf(dA, h, delta * sB[l][nl] * xcv);
            float yv = h * sC[l][nl];
            yv += __shfl_xor_sync(0xffffffffu, yv, 1);
            yv += __shfl_xor_sync(0xffffffffu, yv, 2);
            yv += __shfl_xor_sync(0xffffffffu, yv, 4);
            yv += __shfl_xor_sync(0xffffffffu, yv, 8);
            if (nl == 0) {
                float zl = __half2float(zrow[l]);
                float silu = zl / (1.f + __expf(-zl));
                g_y[(size_t)(base + l) * DIN + d] =
                    __float2half((yv + Dd * xcv) * silu);
            }
        }
    }
}

// ---------------- K7: residual + output LayerNorm, write (B,C,L,1) ----------
__global__ void ln_out_kernel(const float* __restrict__ x,
                              const float* __restrict__ w,
                              const float* __restrict__ bias,
                              float* __restrict__ out) {
    int b  = blockIdx.y;
    int lx = threadIdx.x;
    int ty = threadIdx.y;
    int l  = blockIdx.x * 32 + lx;
    __shared__ float sS[8][32], sQ[8][32], sMean[32], sR[32];

    const float* xb = x + (size_t)b * CDIM * LSEQ + l;
    const float* ob = g_op + (size_t)b * LSEQ + l;
    float s = 0.f, q = 0.f;
    for (int c = ty; c < CDIM; c += 8) {
        float v = ob[(size_t)c * NT] + xb[(size_t)c * LSEQ];
        s += v; q += v * v;
    }
    sS[ty][lx] = s; sQ[ty][lx] = q;
    __syncthreads();
    if (ty == 0) {
        float ts = 0.f, tq = 0.f;
        #pragma unroll
        for (int i = 0; i < 8; i++) { ts += sS[i][lx]; tq += sQ[i][lx]; }
        float m   = ts * (1.f / CDIM);
        float var = tq * (1.f / CDIM) - m * m;
        sMean[lx] = m;
        sR[lx]    = rsqrtf(var + 1e-5f);
    }
    __syncthreads();
    float m = sMean[lx], r = sR[lx];
    float* outb = out + (size_t)b * CDIM * LSEQ + l;
    for (int c = ty; c < CDIM; c += 8) {
        float v = ob[(size_t)c * NT] + xb[(size_t)c * LSEQ];
        outb[(size_t)c * LSEQ] = (v - m) * r * w[c] + bias[c];
    }
}

// ---------------- launch -----------------------------------------------------
extern "C" void kernel_launch(void* const* d_in, const int* in_sizes, int n_in,
                              void* d_out, int out_size) {
    const float* x         = (const float*)d_in[0];
    const float* ln_w      = (const float*)d_in[1];
    const float* ln_b      = (const float*)d_in[2];
    const float* in_proj_w = (const float*)d_in[3];
    const float* conv_w    = (const float*)d_in[4];
    const float* conv_b    = (const float*)d_in[5];
    const float* x_proj_w  = (const float*)d_in[6];
    const float* dt_proj_w = (const float*)d_in[7];
    const float* dt_proj_b = (const float*)d_in[8];
    const float* A_log     = (const float*)d_in[9];
    const float* Dv        = (const float*)d_in[10];
    const float* out_proj_w= (const float*)d_in[11];
    float* out = (float*)d_out;

    __half *p_u, *p_xz, *p_y, *p_wi, *p_wo;
    float  *p_op;
    cudaGetSymbolAddress((void**)&p_u,  g_u);
    cudaGetSymbolAddress((void**)&p_xz, g_xz);
    cudaGetSymbolAddress((void**)&p_y,  g_y);
    cudaGetSymbolAddress((void**)&p_wi, g_wi);
    cudaGetSymbolAddress((void**)&p_wo, g_wo);
    cudaGetSymbolAddress((void**)&p_op, g_op);

    cvtw_kernel<<<(2 * DIN * CDIM + CDIM * DIN) / 256, 256>>>(in_proj_w, out_proj_w);

    ln_in_kernel<<<dim3(LSEQ / 32, BATCH), 256>>>(x, ln_w, ln_b);

    // in_proj: (1024,256) @ (8192,256)^T -> fp16 output
    gemm_h_kernel<__half><<<dim3(NT / 64, (2 * DIN) / 128), 256>>>(
        p_wi, p_u, p_xz, 2 * DIN, NT, CDIM);

    xproj_part_kernel<<<dim3(NT / 64, 4), 256>>>(x_proj_w, conv_w, conv_b);
    xred_kernel<<<(48 * NT) / 256, 256>>>();

    delta_kernel<<<dim3(NT / 256, 4), 256>>>(dt_proj_w, dt_proj_b);

    scan_p1_kernel<<<dim3(4, NCHUNK, BATCH), 256>>>(A_log);
    scan_p2_kernel<<<dim3(BATCH * DIN * 16 / 256), 256>>>();
    scan_p3_kernel<<<dim3(4, NCHUNK, BATCH), 256>>>(A_log, Dv);

    // out_proj: (256,512) @ (8192,512)^T -> fp32 output
    gemm_h_kernel<float><<<dim3(NT / 64, CDIM / 128), 256>>>(
        p_wo, p_y, p_op, CDIM, NT, DIN);

    ln_out_kernel<<<dim3(LSEQ / 32, BATCH), dim3(32, 8)>>>(x, ln_w, ln_b, out);
}

// round 17
// speedup vs baseline: 1.4135x; 1.3792x over previous
#include <cuda_runtime.h>
#include <cuda_fp16.h>
#include <math.h>
#include <stdint.h>

#define LSEQ   2048
#define BATCH  4
#define NT     8192          // BATCH * LSEQ
#define CDIM   256
#define DIN    512
#define DSTATE 16
#define DTRANK 16
#define NCHUNK 32
#define CHLEN  64            // LSEQ / NCHUNK

// ---------------- scratch (static __device__, no allocs) ----------------
__device__ __half g_u    [NT * CDIM];       // (B*L, C) normalized input (fp16)
__device__ __half g_xz   [2 * DIN * NT];    // (2*DIN, B*L) in_proj out (fp16)
__device__ __half g_xc   [DIN * NT];        // (DIN, B*L) conv+silu (fp16)
__device__ float  g_xpart[4 * 48 * NT];     // x_proj split-K partials
__device__ float  g_dt   [NT * DTRANK];     // (B*L, 16)
__device__ float  g_Bm   [NT * DSTATE];     // (B*L, 16)
__device__ float  g_Cm   [NT * DSTATE];     // (B*L, 16)
__device__ __half g_delta[DIN * NT];        // (DIN, B*L) softplus (fp16)
__device__ __half g_y    [NT * DIN];        // (B*L, DIN) gated y (fp16)
__device__ float  g_op   [CDIM * NT];       // (C, B*L) out_proj out
__device__ float  g_P    [BATCH * NCHUNK * DIN * DSTATE];
__device__ float  g_q    [BATCH * NCHUNK * DIN * DSTATE];
__device__ float  g_h0   [BATCH * NCHUNK * DIN * DSTATE];

__device__ __forceinline__ uint32_t s2u(const void* p) {
    return (uint32_t)__cvta_generic_to_shared(p);
}
__device__ __forceinline__ void ldsm4(uint32_t* r, uint32_t addr) {
    asm volatile("ldmatrix.sync.aligned.m8n8.x4.shared.b16 {%0,%1,%2,%3}, [%4];"
        : "=r"(r[0]), "=r"(r[1]), "=r"(r[2]), "=r"(r[3]) : "r"(addr));
}
__device__ __forceinline__ void mma16816h(float* c, const uint32_t* a, uint32_t b0, uint32_t b1) {
    asm volatile("mma.sync.aligned.m16n8k16.row.col.f32.f16.f16.f32 "
        "{%0,%1,%2,%3}, {%4,%5,%6,%7}, {%8,%9}, {%0,%1,%2,%3};"
        : "+f"(c[0]), "+f"(c[1]), "+f"(c[2]), "+f"(c[3])
        : "r"(a[0]), "r"(a[1]), "r"(a[2]), "r"(a[3]), "r"(b0), "r"(b1));
}

// ---------------- K1: input LayerNorm (over C), emit fp16 (NT, C) -----------
__global__ void ln_in_kernel(const float* __restrict__ x,
                             const float* __restrict__ w,
                             const float* __restrict__ bias) {
    int b  = blockIdx.y;
    int tid = threadIdx.x;
    int lx = tid & 31;
    int ty = tid >> 5;
    int l0 = blockIdx.x * 32;
    __shared__ float T[CDIM][33];
    __shared__ float sS[8][32], sQ[8][32], sMean[32], sR[32];

    const float* xb = x + (size_t)b * CDIM * LSEQ + l0 + lx;
    float s = 0.f, q = 0.f;
    for (int c = ty; c < CDIM; c += 8) {
        float v = xb[(size_t)c * LSEQ];
        T[c][lx] = v;
        s += v; q += v * v;
    }
    sS[ty][lx] = s; sQ[ty][lx] = q;
    __syncthreads();
    if (ty == 0) {
        float ts = 0.f, tq = 0.f;
        #pragma unroll
        for (int i = 0; i < 8; i++) { ts += sS[i][lx]; tq += sQ[i][lx]; }
        float m   = ts * (1.f / CDIM);
        float var = tq * (1.f / CDIM) - m * m;
        sMean[lx] = m;
        sR[lx]    = rsqrtf(var + 1e-5f);
    }
    __syncthreads();
    int c = tid;
    float wc = w[c], bc = bias[c];
    #pragma unroll 4
    for (int l = 0; l < 32; l++) {
        float v = T[c][l];
        g_u[(size_t)(b * LSEQ + l0 + l) * CDIM + c] =
            __float2half((v - sMean[l]) * sR[l] * wc + bc);
    }
}

// ---------------- K2: TN GEMM, fp32 A (cvt in-kernel) x fp16 B --------------
template <typename OutT>
__global__ __launch_bounds__(256, 2)
void gemm_h_kernel(const float* __restrict__ A, const __half* __restrict__ Bg,
                   OutT* __restrict__ C, int M, int N, int K) {
    __shared__ __half Ah[128][40], Bh[64][40];
    const int tid = threadIdx.x, lane = tid & 31, wid = tid >> 5;
    const int m0 = blockIdx.y * 128, n0 = blockIdx.x * 64;
    const int wm = (wid & 3) * 32;
    const int wn = (wid >> 2) * 32;
    const int lr = lane & 15;
    const int lc = (lane & 16) ? 8 : 0;

    float acc[2][4][4];
    #pragma unroll
    for (int mi = 0; mi < 2; mi++)
        #pragma unroll
        for (int nf = 0; nf < 4; nf++)
            #pragma unroll
            for (int e = 0; e < 4; e++) acc[mi][nf][e] = 0.f;

    const int grow = tid >> 3;           // 0..31  (A loader)
    const int gcol = (tid & 7) << 2;     // 0..28
    const int br = tid >> 2;             // 0..63  (B loader)
    const int bc8 = (tid & 3) << 3;      // 0,8,16,24 halves

    const float*  Abase = A  + (size_t)(m0 + grow) * K + gcol;
    const __half* Bbase = Bg + (size_t)(n0 + br) * K + bc8;

    float4 va[4];
    uint4  vb;
    #pragma unroll
    for (int i = 0; i < 4; i++) va[i] = *(const float4*)(Abase + (size_t)(32 * i) * K);
    vb = *(const uint4*)(Bbase);

    const int nk = K >> 5;
    for (int kt = 0; kt < nk; kt++) {
        #pragma unroll
        for (int i = 0; i < 4; i++) {
            int r = grow + 32 * i;
            float4 v = va[i];
            __half2 hh0, hh1;
            hh0.x = __float2half(v.x); hh0.y = __float2half(v.y);
            hh1.x = __float2half(v.z); hh1.y = __float2half(v.w);
            *(__half2*)&Ah[r][gcol]     = hh0;
            *(__half2*)&Ah[r][gcol + 2] = hh1;
        }
        *(uint4*)&Bh[br][bc8] = vb;
        __syncthreads();

        if (kt + 1 < nk) {
            const float*  Ap = Abase + (kt + 1) * 32;
            const __half* Bp = Bbase + (kt + 1) * 32;
            #pragma unroll
            for (int i = 0; i < 4; i++) va[i] = *(const float4*)(Ap + (size_t)(32 * i) * K);
            vb = *(const uint4*)(Bp);
        }

        #pragma unroll
        for (int kk = 0; kk < 2; kk++) {
            const int k16 = kk * 16;
            uint32_t ah[2][4], bh[2][4];
            #pragma unroll
            for (int mi = 0; mi < 2; mi++)
                ldsm4(ah[mi], s2u(&Ah[wm + mi * 16 + lr][k16 + lc]));
            #pragma unroll
            for (int nj = 0; nj < 2; nj++)
                ldsm4(bh[nj], s2u(&Bh[wn + nj * 16 + lr][k16 + lc]));
            #pragma unroll
            for (int mi = 0; mi < 2; mi++)
                #pragma unroll
                for (int nf = 0; nf < 4; nf++) {
                    int nj = nf >> 1, sub = nf & 1;
                    mma16816h(acc[mi][nf], ah[mi], bh[nj][sub], bh[nj][sub + 2]);
                }
        }
        __syncthreads();
    }

    #pragma unroll
    for (int mi = 0; mi < 2; mi++)
        #pragma unroll
        for (int nf = 0; nf < 4; nf++) {
            int row = m0 + wm + mi * 16 + (lane >> 2);
            int col = n0 + wn + nf * 8 + ((lane & 3) << 1);
            if constexpr (sizeof(OutT) == 2) {
                __half2 h0, h1;
                h0.x = __float2half(acc[mi][nf][0]); h0.y = __float2half(acc[mi][nf][1]);
                h1.x = __float2half(acc[mi][nf][2]); h1.y = __float2half(acc[mi][nf][3]);
                *(__half2*)&C[(size_t)row * N + col]       = h0;
                *(__half2*)&C[(size_t)(row + 8) * N + col] = h1;
            } else {
                float2 v0; v0.x = acc[mi][nf][0]; v0.y = acc[mi][nf][1];
                float2 v1; v1.x = acc[mi][nf][2]; v1.y = acc[mi][nf][3];
                *(float2*)&C[(size_t)row * N + col]       = v0;
                *(float2*)&C[(size_t)(row + 8) * N + col] = v1;
            }
        }
}

// ---------------- K3: x_proj split-K partials + fused conv+SiLU -------------
// Ws stored TRANSPOSED (WsT[dd][k]): inner product reads 3 broadcast float4
// per dd instead of 12 scalar LDS.
__global__ void xproj_part_kernel(const float* __restrict__ W,
                                  const float* __restrict__ cw,
                                  const float* __restrict__ cb) {
    __shared__ float WsT[64][52];
    __shared__ float Xr[64][68];
    __shared__ float Xs[64][68];
    __shared__ float Cw[64][4];
    __shared__ float Cb[64];
    int t  = threadIdx.x;
    int n0 = blockIdx.x * 64;
    int ks = blockIdx.y;
    int tn = t & 63, tk = t >> 6;
    bool seqstart = (n0 & (LSEQ - 1)) == 0;
    float acc[12];
    #pragma unroll
    for (int j = 0; j < 12; j++) acc[j] = 0.f;

    for (int cc = 0; cc < 2; cc++) {
        int d0 = ks * 128 + cc * 64;
        __syncthreads();
        for (int i = t; i < 48 * 64; i += 256) {
            int k = i >> 6, dd = i & 63;
            WsT[dd][k] = W[(size_t)k * DIN + d0 + dd];
        }
        if (t < 64) {
            *(float4*)&Cw[t][0] = *(const float4*)&cw[(d0 + t) * 4];
            Cb[t] = cb[d0 + t];
        }
        for (int i = t; i < 512; i += 256) {
            int r = i >> 3, c8 = (i & 7) << 3;
            uint4 raw = *(const uint4*)&g_xz[(size_t)(d0 + r) * NT + n0 + c8];
            const __half2* hp = (const __half2*)&raw;
            #pragma unroll
            for (int j = 0; j < 4; j++) {
                float2 f = __half22float2(hp[j]);
                Xr[r][4 + c8 + j * 2]     = f.x;
                Xr[r][4 + c8 + j * 2 + 1] = f.y;
            }
        }
        if (t < 192) {
            int r = t / 3, j = t - r * 3;
            Xr[r][1 + j] = seqstart ? 0.f
                : __half2float(g_xz[(size_t)(d0 + r) * NT + n0 - 3 + j]);
        }
        __syncthreads();
        for (int i = t; i < 4096; i += 256) {
            int r = i >> 6, c = i & 63;
            float v = Cb[r];
            v = fmaf(Cw[r][3], Xr[r][c + 4], v);
            v = fmaf(Cw[r][2], Xr[r][c + 3], v);
            v = fmaf(Cw[r][1], Xr[r][c + 2], v);
            v = fmaf(Cw[r][0], Xr[r][c + 1], v);
            float xc = v / (1.f + __expf(-v));
            Xs[r][c] = xc;
            g_xc[(size_t)(d0 + r) * NT + n0 + c] = __float2half(xc);
        }
        __syncthreads();
        #pragma unroll 4
        for (int dd = 0; dd < 64; dd++) {
            float xv = Xs[dd][tn];
            float4 w0 = *(float4*)&WsT[dd][tk * 12];
            float4 w1 = *(float4*)&WsT[dd][tk * 12 + 4];
            float4 w2 = *(float4*)&WsT[dd][tk * 12 + 8];
            acc[0]  = fmaf(xv, w0.x, acc[0]);  acc[1]  = fmaf(xv, w0.y, acc[1]);
            acc[2]  = fmaf(xv, w0.z, acc[2]);  acc[3]  = fmaf(xv, w0.w, acc[3]);
            acc[4]  = fmaf(xv, w1.x, acc[4]);  acc[5]  = fmaf(xv, w1.y, acc[5]);
            acc[6]  = fmaf(xv, w1.z, acc[6]);  acc[7]  = fmaf(xv, w1.w, acc[7]);
            acc[8]  = fmaf(xv, w2.x, acc[8]);  acc[9]  = fmaf(xv, w2.y, acc[9]);
            acc[10] = fmaf(xv, w2.z, acc[10]); acc[11] = fmaf(xv, w2.w, acc[11]);
        }
    }
    int n = n0 + tn;
    #pragma unroll
    for (int j = 0; j < 12; j++) {
        int k = tk * 12 + j;
        g_xpart[((size_t)ks * 48 + k) * NT + n] = acc[j];
    }
}

// ---------------- K4: reduce partials -> dt/Bm/Cm in (n,16) layout ----------
__global__ void xred_kernel() {
    int idx = blockIdx.x * 256 + threadIdx.x;       // 48 * NT
    int k = idx / NT, n = idx - k * NT;
    float s = g_xpart[(size_t)k * NT + n]
            + g_xpart[((size_t)48 + k) * NT + n]
            + g_xpart[((size_t)96 + k) * NT + n]
            + g_xpart[((size_t)144 + k) * NT + n];
    if (k < DTRANK)                g_dt[(size_t)n * 16 + k] = s;
    else if (k < DTRANK + DSTATE)  g_Bm[(size_t)n * 16 + (k - DTRANK)] = s;
    else                           g_Cm[(size_t)n * 16 + (k - DTRANK - DSTATE)] = s;
}

// ---------------- K5: delta = softplus(dt @ dtw^T + dtb), smem-tiled --------
__global__ void delta_kernel(const float* __restrict__ dtw,
                             const float* __restrict__ dtb) {
    __shared__ float sDt[256][17];
    __shared__ float sW[128][17];
    __shared__ float sB[128];
    int t = threadIdx.x;
    int n0 = blockIdx.x * 256;
    int dseg = blockIdx.y * 128;

    for (int i = t; i < 256 * 4; i += 256) {
        int r = i >> 2, c4 = (i & 3) << 2;
        float4 v = *(const float4*)&g_dt[(size_t)(n0 + r) * 16 + c4];
        sDt[r][c4 + 0] = v.x; sDt[r][c4 + 1] = v.y;
        sDt[r][c4 + 2] = v.z; sDt[r][c4 + 3] = v.w;
    }
    for (int i = t; i < 128 * 4; i += 256) {
        int r = i >> 2, c4 = (i & 3) << 2;
        float4 v = *(const float4*)&dtw[(size_t)(dseg + r) * 16 + c4];
        sW[r][c4 + 0] = v.x; sW[r][c4 + 1] = v.y;
        sW[r][c4 + 2] = v.z; sW[r][c4 + 3] = v.w;
    }
    if (t < 128) sB[t] = dtb[dseg + t];
    __syncthreads();

    int n = n0 + t;
    for (int dd = 0; dd < 128; dd++) {
        float s = sB[dd];
        #pragma unroll
        for (int k = 0; k < 16; k++)
            s = fmaf(sDt[t][k], sW[dd][k], s);
        float delta = (s > 20.f) ? s : log1pf(__expf(s));
        g_delta[(size_t)(dseg + dd) * NT + n] = __float2half(delta);
    }
}

// ---------------- K6a: chunk scan pass1 — smem-shared B chunk ---------------
__global__ void scan_p1_kernel(const float* __restrict__ Alog) {
    __shared__ float sB[CHLEN][16];
    int b  = blockIdx.z;
    int ch = blockIdx.y;
    int g  = threadIdx.x >> 4;
    int nl = threadIdx.x & 15;
    int d0 = blockIdx.x * 128;
    int base = b * LSEQ + ch * CHLEN;

    {
        int t = threadIdx.x;
        float4 v = *(const float4*)&g_Bm[((size_t)base) * 16 + t * 4];
        *(float4*)&sB[(t * 4) >> 4][(t * 4) & 15] = v;
    }
    __syncthreads();

    for (int dt = 0; dt < 8; dt++) {
        int d = d0 + dt * 16 + g;
        float Adn = -__expf(Alog[d * DSTATE + nl]);
        float P = 1.f, q = 0.f;
        const __half* drow  = g_delta + (size_t)d * NT + base;
        const __half* xcrow = g_xc    + (size_t)d * NT + base;
        #pragma unroll 4
        for (int l = 0; l < CHLEN; l++) {
            float delta = __half2float(drow[l]);
            float dA = __expf(delta * Adn);
            q = fmaf(dA, q, delta * sB[l][nl] * __half2float(xcrow[l]));
            P *= dA;
        }
        size_t idx = ((size_t)(b * NCHUNK + ch) * DIN + d) * 16 + nl;
        g_P[idx] = P;
        g_q[idx] = q;
    }
}

// ---------------- K6b: prefix over chunks -> h0 -----------------------------
__global__ void scan_p2_kernel() {
    int idx = blockIdx.x * 256 + threadIdx.x;
    int n = idx & 15;
    int d = (idx >> 4) & (DIN - 1);
    int b = idx >> 13;
    float h = 0.f;
    #pragma unroll
    for (int ch = 0; ch < NCHUNK; ch++) {
        size_t p = ((size_t)(b * NCHUNK + ch) * DIN + d) * 16 + n;
        g_h0[p] = h;
        h = fmaf(g_P[p], h, g_q[p]);
    }
}

// ---------------- K6c: replay + y + gating — register-state, no shuffles ----
__global__ __launch_bounds__(128)
void scan_p3_kernel(const float* __restrict__ Alog,
                    const float* __restrict__ Dp) {
    __shared__ float sB[CHLEN][16];
    __shared__ float sC[CHLEN][16];
    int b  = blockIdx.z;
    int ch = blockIdx.y;
    int d  = blockIdx.x * 128 + threadIdx.x;
    int base = b * LSEQ + ch * CHLEN;

    {
        int t = threadIdx.x;           // 128 threads x 8 floats = 1024 = 64*16
        int off = t * 8;
        float4 v0 = *(const float4*)&g_Bm[(size_t)base * 16 + off];
        float4 v1 = *(const float4*)&g_Bm[(size_t)base * 16 + off + 4];
        *(float4*)&sB[off >> 4][off & 15]             = v0;
        *(float4*)&sB[(off + 4) >> 4][(off + 4) & 15] = v1;
        float4 w0 = *(const float4*)&g_Cm[(size_t)base * 16 + off];
        float4 w1 = *(const float4*)&g_Cm[(size_t)base * 16 + off + 4];
        *(float4*)&sC[off >> 4][off & 15]             = w0;
        *(float4*)&sC[(off + 4) >> 4][(off + 4) & 15] = w1;
    }
    __syncthreads();

    float Adn[16], h[16];
    #pragma unroll
    for (int n = 0; n < 16; n++)
        Adn[n] = -__expf(Alog[d * DSTATE + n]);
    const float* h0p = &g_h0[((size_t)(b * NCHUNK + ch) * DIN + d) * 16];
    #pragma unroll
    for (int n4 = 0; n4 < 4; n4++) {
        float4 v = *(const float4*)(h0p + n4 * 4);
        h[n4 * 4 + 0] = v.x; h[n4 * 4 + 1] = v.y;
        h[n4 * 4 + 2] = v.z; h[n4 * 4 + 3] = v.w;
    }
    float Dd = Dp[d];
    const __half* drow  = g_delta + (size_t)d * NT + base;
    const __half* xcrow = g_xc    + (size_t)d * NT + base;
    const __half* zrow  = g_xz + (size_t)(DIN + d) * NT + base;

    for (int l = 0; l < CHLEN; l++) {
        float delta = __half2float(drow[l]);
        float xcv = __half2float(xcrow[l]);
        float dxc = delta * xcv;
        float y = 0.f;
        #pragma unroll
        for (int n = 0; n < 16; n++) {
            float dA = __expf(delta * Adn[n]);
            h[n] = fmaf(dA, h[n], dxc * sB[l][n]);
            y = fmaf(h[n], sC[l][n], y);
        }
        float zl = __half2float(zrow[l]);
        float silu = zl / (1.f + __expf(-zl));
        g_y[(size_t)(base + l) * DIN + d] = __float2half((y + Dd * xcv) * silu);
    }
}

// ---------------- K7: residual + output LayerNorm, write (B,C,L,1) ----------
__global__ void ln_out_kernel(const float* __restrict__ x,
                              const float* __restrict__ w,
                              const float* __restrict__ bias,
                              float* __restrict__ out) {
    int b  = blockIdx.y;
    int lx = threadIdx.x;
    int ty = threadIdx.y;
    int l  = blockIdx.x * 32 + lx;
    __shared__ float sS[8][32], sQ[8][32], sMean[32], sR[32];

    const float* xb = x + (size_t)b * CDIM * LSEQ + l;
    const float* ob = g_op + (size_t)b * LSEQ + l;
    float s = 0.f, q = 0.f;
    for (int c = ty; c < CDIM; c += 8) {
        float v = ob[(size_t)c * NT] + xb[(size_t)c * LSEQ];
        s += v; q += v * v;
    }
    sS[ty][lx] = s; sQ[ty][lx] = q;
    __syncthreads();
    if (ty == 0) {
        float ts = 0.f, tq = 0.f;
        #pragma unroll
        for (int i = 0; i < 8; i++) { ts += sS[i][lx]; tq += sQ[i][lx]; }
        float m   = ts * (1.f / CDIM);
        float var = tq * (1.f / CDIM) - m * m;
        sMean[lx] = m;
        sR[lx]    = rsqrtf(var + 1e-5f);
    }
    __syncthreads();
    float m = sMean[lx], r = sR[lx];
    float* outb = out + (size_t)b * CDIM * LSEQ + l;
    for (int c = ty; c < CDIM; c += 8) {
        float v = ob[(size_t)c * NT] + xb[(size_t)c * LSEQ];
        outb[(size_t)c * LSEQ] = (v - m) * r * w[c] + bias[c];
    }
}

// ---------------- launch -----------------------------------------------------
extern "C" void kernel_launch(void* const* d_in, const int* in_sizes, int n_in,
                              void* d_out, int out_size) {
    const float* x         = (const float*)d_in[0];
    const float* ln_w      = (const float*)d_in[1];
    const float* ln_b      = (const float*)d_in[2];
    const float* in_proj_w = (const float*)d_in[3];
    const float* conv_w    = (const float*)d_in[4];
    const float* conv_b    = (const float*)d_in[5];
    const float* x_proj_w  = (const float*)d_in[6];
    const float* dt_proj_w = (const float*)d_in[7];
    const float* dt_proj_b = (const float*)d_in[8];
    const float* A_log     = (const float*)d_in[9];
    const float* Dv        = (const float*)d_in[10];
    const float* out_proj_w= (const float*)d_in[11];
    float* out = (float*)d_out;

    __half *p_u, *p_xz, *p_y;
    float  *p_op;
    cudaGetSymbolAddress((void**)&p_u,  g_u);
    cudaGetSymbolAddress((void**)&p_xz, g_xz);
    cudaGetSymbolAddress((void**)&p_y,  g_y);
    cudaGetSymbolAddress((void**)&p_op, g_op);

    ln_in_kernel<<<dim3(LSEQ / 32, BATCH), 256>>>(x, ln_w, ln_b);

    // in_proj: (1024,256) @ (8192,256)^T -> fp16 output
    gemm_h_kernel<__half><<<dim3(NT / 64, (2 * DIN) / 128), 256>>>(
        in_proj_w, p_u, p_xz, 2 * DIN, NT, CDIM);

    xproj_part_kernel<<<dim3(NT / 64, 4), 256>>>(x_proj_w, conv_w, conv_b);
    xred_kernel<<<(48 * NT) / 256, 256>>>();

    delta_kernel<<<dim3(NT / 256, 4), 256>>>(dt_proj_w, dt_proj_b);

    scan_p1_kernel<<<dim3(4, NCHUNK, BATCH), 256>>>(A_log);
    scan_p2_kernel<<<dim3(BATCH * DIN * 16 / 256), 256>>>();
    scan_p3_kernel<<<dim3(DIN / 128, NCHUNK, BATCH), 128>>>(A_log, Dv);

    // out_proj: (256,512) @ (8192,512)^T -> fp32 output
    gemm_h_kernel<float><<<dim3(NT / 64, CDIM / 128), 256>>>(
        out_proj_w, p_y, p_op, CDIM, NT, DIN);

    ln_out_kernel<<<dim3(LSEQ / 32, BATCH), dim3(32, 8)>>>(x, ln_w, ln_b, out);
}